// round 11
// baseline (speedup 1.0000x reference)
#include <cuda_runtime.h>
#include <cstdint>

#define NB 32
#define KB 32
#define TB 128
#define HB 768
#define H2 1536

// Output layout (float32, concat of flattened outputs)
#define OFF_SCORE   0
#define OFF_ENC     1024
#define OFF_MASK    3146752
#define OFF_USE     3150848
#define OFF_IDX     3175424

#define USPLIT 8
#define GCH    (HB / USPLIT)   // 96

// Bid layout:
//   [0,1152):   triplets (A, A, Gather) — 768 A blocks + 384 gather blocks
//               interleaved so wave 1 co-runs the GEMM and the 12 MB gather.
//   [1152,1344): 192 u split-K blocks   (spin on cntA == 768)
//   1344:        c block                (spin on cntA == 768)
//   [1345,1473): 128 score blocks      (spin on cntU == 193)
//   [1473,1505): 32 small-gather blocks
#define B_MIX   1152
#define B_U0    1152
#define B_C     1344
#define B_S0    1345
#define B_SM0   1473
#define GRID_T  1505

#define NPROD_A 768
#define NPROD_U 193

// Scratch (device globals — allocation is forbidden)
__device__ float    g_cqk_pro[NB * HB];
__device__ float    g_upart[USPLIT][NB][HB];
__device__ float    g_c[NB];
__device__ unsigned g_cntA, g_cntU, g_done;

__device__ __forceinline__ unsigned ld_acq(const unsigned* p) {
    unsigned v;
    asm volatile("ld.global.acquire.gpu.u32 %0, [%1];" : "=r"(v) : "l"(p));
    return v;
}

__global__ void __launch_bounds__(256) mega(
    const float* __restrict__ ctx1,
    const float* __restrict__ tku,
    const float* __restrict__ pe0,
    const float* __restrict__ pe1,
    const int*   __restrict__ pm,
    const int*   __restrict__ ckm,
    const int*   __restrict__ label,
    const int*   __restrict__ pt,
    const float* __restrict__ Wcqk,
    const float* __restrict__ bcqk,
    const float* __restrict__ Wk,
    const float* __restrict__ bk,
    float* __restrict__ out)
{
    const int b    = blockIdx.x;
    const int tid  = threadIdx.x;
    const int wid  = tid >> 5;
    const int lane = tid & 31;

    if (b < B_MIX) {
        const int trip = b / 3;
        const int rem  = b - trip * 3;
        if (rem < 2) {
            // ================= A-GEMM block (a_idx = 2*trip + rem, 0..767)
            const int a_idx = 2 * trip + rem;
            const int gw = a_idx * 8 + wid;      // 0..6143
            const int hg = gw >> 5;              // same for whole block
            const int n  = gw & 31;
            const int h0 = hg * 4;

            float4 a[12];
            const float4* arow0 = (const float4*)(ctx1 + (size_t)n * 3 * HB + 2 * HB);
            const float4* arow1 = (const float4*)(tku  + (size_t)n * HB);
#pragma unroll
            for (int i = 0; i < 6; i++) a[i]     = arow0[i * 32 + lane];
#pragma unroll
            for (int i = 0; i < 6; i++) a[i + 6] = arow1[i * 32 + lane];

            float acc[4];
#pragma unroll
            for (int hh = 0; hh < 4; hh++) {
                const float4* w = (const float4*)(Wcqk + (size_t)(h0 + hh) * H2);
                float s = 0.f;
#pragma unroll
                for (int i = 0; i < 12; i++) {
                    float4 wv = w[i * 32 + lane];
                    s += a[i].x * wv.x + a[i].y * wv.y + a[i].z * wv.z + a[i].w * wv.w;
                }
                acc[hh] = s;
            }
#pragma unroll
            for (int hh = 0; hh < 4; hh++) {
#pragma unroll
                for (int o = 16; o; o >>= 1)
                    acc[hh] += __shfl_xor_sync(0xFFFFFFFFu, acc[hh], o);
            }
            if (lane == 0) {
                float* dst = g_cqk_pro + (size_t)n * HB + h0;
                dst[0] = acc[0] + bcqk[h0 + 0];
                dst[1] = acc[1] + bcqk[h0 + 1];
                dst[2] = acc[2] + bcqk[h0 + 2];
                dst[3] = acc[3] + bcqk[h0 + 3];
            }
            __threadfence();
            __syncthreads();
            if (tid == 0) atomicAdd(&g_cntA, 1u);
        } else {
            // ================= big-gather block (g_idx = trip, 0..383)
            const int n     = trip / 12;         // 12 blocks per n
            const int chunk = trip % 12;
            const float4* src = (const float4*)(pe0 + ((size_t)n * KB + label[n]) * (size_t)TB * HB);
            float4* dst = (float4*)(out + OFF_ENC + (size_t)n * TB * HB);
            const int i0 = chunk * 2048 + tid;
#pragma unroll
            for (int j = 0; j < 8; j++)
                dst[i0 + j * 256] = src[i0 + j * 256];
        }

    } else if (b < B_C) {
        // ================= u split-K: g_upart[split][n][h0..h0+3]
        const int bb    = b - B_U0;          // 0..191
        const int htile = bb >> 5;           // 0..5, same for block
        const int rem   = bb & 31;
        const int split = rem >> 2;          // same for block
        const int ng    = rem & 3;
        const int n     = ng * 8 + wid;
        const int h0    = htile * 128 + lane * 4;
        const int g0    = split * GCH;

        if (tid == 0) {
            while (ld_acq(&g_cntA) < (unsigned)NPROD_A) __nanosleep(32);
        }
        __syncthreads();

        const float4* wrow = (const float4*)(Wk + (size_t)g0 * HB + h0);
        const float*  cr   = g_cqk_pro + (size_t)n * HB + g0;

        float4 acc0 = {0.f, 0.f, 0.f, 0.f};
        float4 acc1 = {0.f, 0.f, 0.f, 0.f};
#pragma unroll
        for (int gb = 0; gb < GCH; gb += 32) {
            float cg = cr[gb + lane];
            const float4* wb = wrow + (size_t)gb * (HB / 4);
#pragma unroll
            for (int j = 0; j < 32; j += 2) {
                float c0 = __shfl_sync(0xFFFFFFFFu, cg, j);
                float c1 = __shfl_sync(0xFFFFFFFFu, cg, j + 1);
                float4 w0 = wb[(size_t)j * (HB / 4)];
                float4 w1 = wb[(size_t)(j + 1) * (HB / 4)];
                acc0.x += c0 * w0.x; acc0.y += c0 * w0.y;
                acc0.z += c0 * w0.z; acc0.w += c0 * w0.w;
                acc1.x += c1 * w1.x; acc1.y += c1 * w1.y;
                acc1.z += c1 * w1.z; acc1.w += c1 * w1.w;
            }
        }
        float4 r;
        r.x = acc0.x + acc1.x; r.y = acc0.y + acc1.y;
        r.z = acc0.z + acc1.z; r.w = acc0.w + acc1.w;
        *(float4*)(&g_upart[split][n][h0]) = r;

        __threadfence();
        __syncthreads();
        if (tid == 0) atomicAdd(&g_cntU, 1u);

    } else if (b == B_C) {
        // ================= c[n] = bk . cqk_pro[n,:]
        if (tid == 0) {
            while (ld_acq(&g_cntA) < (unsigned)NPROD_A) __nanosleep(32);
        }
        __syncthreads();
#pragma unroll
        for (int r = 0; r < 4; r++) {
            const int n = wid + r * 8;
            const float4* cc  = (const float4*)(g_cqk_pro + (size_t)n * HB);
            const float4* bb4 = (const float4*)bk;
            float s = 0.f;
#pragma unroll
            for (int i = 0; i < 6; i++) {
                float4 x = cc[i * 32 + lane];
                float4 y = bb4[i * 32 + lane];
                s += x.x * y.x + x.y * y.y + x.z * y.z + x.w * y.w;
            }
#pragma unroll
            for (int o = 16; o; o >>= 1) s += __shfl_xor_sync(0xFFFFFFFFu, s, o);
            if (lane == 0) g_c[n] = s;
        }
        __threadfence();
        __syncthreads();
        if (tid == 0) atomicAdd(&g_cntU, 1u);

    } else if (b < B_SM0) {
        // ================= score: prefetch pe1, spin, sum partials, dot
        const int bb = b - B_S0;
        const int n  = bb >> 2;
        const int kg = bb & 3;
        const int k  = kg * 8 + wid;

        const float4* p = (const float4*)(pe1 + ((size_t)n * KB + k) * HB);
        float4 a[6];
#pragma unroll
        for (int i = 0; i < 6; i++) a[i] = p[i * 32 + lane];

        const int mask_v = ckm[n * KB + k];

        if (tid == 0) {
            while (ld_acq(&g_cntU) < (unsigned)NPROD_U) __nanosleep(32);
        }
        __syncthreads();

        float s = 0.f;
#pragma unroll
        for (int i = 0; i < 6; i++) {
            const int hh = (i * 32 + lane) * 4;
            float4 q0 = *(const float4*)(&g_upart[0][n][hh]);
#pragma unroll
            for (int sp = 1; sp < USPLIT; sp++) {
                float4 qs = *(const float4*)(&g_upart[sp][n][hh]);
                q0.x += qs.x; q0.y += qs.y; q0.z += qs.z; q0.w += qs.w;
            }
            s += a[i].x * q0.x + a[i].y * q0.y + a[i].z * q0.z + a[i].w * q0.w;
        }
#pragma unroll
        for (int o = 16; o; o >>= 1) s += __shfl_xor_sync(0xFFFFFFFFu, s, o);
        if (lane == 0)
            out[OFF_SCORE + n * KB + k] = (mask_v != 0) ? (s + g_c[n]) : -1e20f;

    } else {
        // ================= small gathers
        const int n    = b - B_SM0;
        const int lab  = label[n];
        const int base = (n * KB + lab) * TB;
        for (int t = tid; t < TB; t += 256) {
            out[OFF_MASK + n * TB + t] = (pm[base + t] != 0) ? 1.f : 0.f;
            out[OFF_IDX  + n * TB + t] = (float)pt[base + t];
        }
        const size_t ub = ((size_t)n * KB + lab) * HB;
        for (int h = tid; h < HB; h += 256)
            out[OFF_USE + n * HB + h] = pe1[ub + h];
    }

    // ---- replay-safe reset: last block out clears the counters
    __syncthreads();
    if (tid == 0) {
        unsigned v = atomicAdd(&g_done, 1u);
        if (v == (unsigned)(GRID_T - 1)) {
            g_cntA = 0u;
            g_cntU = 0u;
            g_done = 0u;
            __threadfence();
        }
    }
}

extern "C" void kernel_launch(void* const* d_in, const int* in_sizes, int n_in,
                              void* d_out, int out_size)
{
    const float* ctx1 = (const float*)d_in[0];
    const float* tku  = (const float*)d_in[1];
    const float* pe0  = (const float*)d_in[2];
    const float* pe1  = (const float*)d_in[3];
    const int*   pm   = (const int*)d_in[4];
    const int*   ckm  = (const int*)d_in[5];
    const int*   lab  = (const int*)d_in[6];
    const int*   pt   = (const int*)d_in[7];
    const float* Wcqk = (const float*)d_in[8];
    const float* bcqk = (const float*)d_in[9];
    const float* Wk   = (const float*)d_in[10];
    const float* bk   = (const float*)d_in[11];

    mega<<<GRID_T, 256>>>(ctx1, tku, pe0, pe1, pm, ckm, lab, pt,
                          Wcqk, bcqk, Wk, bk, (float*)d_out);
}

// round 12
// speedup vs baseline: 1.2618x; 1.2618x over previous
#include <cuda_runtime.h>
#include <cstdint>

#define NB 32
#define KB 32
#define TB 128
#define HB 768
#define H2 1536

// Output layout (float32, concat of flattened outputs)
#define OFF_SCORE   0
#define OFF_ENC     1024
#define OFF_MASK    3146752
#define OFF_USE     3150848
#define OFF_IDX     3175424

#define USPLIT 8
#define GCH    (HB / USPLIT)   // 96

// Scratch (device globals — allocation is forbidden)
__device__ float    g_cqk_pro[NB * HB];
__device__ float    g_upart[USPLIT][NB][HB];
__device__ float    g_sink;
__device__ unsigned g_cntU, g_done;

__device__ __forceinline__ unsigned ld_acq(const unsigned* p) {
    unsigned v;
    asm volatile("ld.global.acquire.gpu.u32 %0, [%1];" : "=r"(v) : "l"(p));
    return v;
}

// ---------------------------------------------------------------------------
// Launch 1 (1604 blocks x 256): independent work + L2 warm of Wk.
//   [0,36):      warm Wk into L2 (__ldcg, 147456 float4 across 36 blocks)
//   [36,804):    big gather shifted_encoded (4 float4 per thread)
//   [804,1572):  A-GEMM  cqk_pro[n,h] = cqk[n,:] . W_cqk[h,:] + b[h]
//   [1572,1604): small gathers
// ---------------------------------------------------------------------------
#define B1_W0   0
#define B1_G0   36
#define B1_A0   804
#define B1_SM0  1572
#define GRID1   1604

__global__ void __launch_bounds__(256) k1_gather_agemm(
    const float* __restrict__ ctx1,
    const float* __restrict__ tku,
    const float* __restrict__ Wcqk,
    const float* __restrict__ bcqk,
    const float* __restrict__ pe0,
    const float* __restrict__ pe1,
    const int*   __restrict__ pm,
    const int*   __restrict__ pt,
    const int*   __restrict__ label,
    const float* __restrict__ Wk,
    float* __restrict__ cqkp,
    float* __restrict__ out)
{
    const int b   = blockIdx.x;
    const int tid = threadIdx.x;

    if (b < B1_G0) {
        // ---- warm Wk into L2: 36 blocks x 256 threads x 16 float4 = 147456
        const float4* wk4 = (const float4*)Wk;
        const int base = b * 4096 + tid;
        float4 acc = {0.f, 0.f, 0.f, 0.f};
#pragma unroll
        for (int j = 0; j < 16; j++) {
            float4 v = __ldcg(&wk4[base + j * 256]);
            acc.x += v.x; acc.y += v.y; acc.z += v.z; acc.w += v.w;
        }
        float s = acc.x + acc.y + acc.z + acc.w;
        if (s == 123456789.0f) g_sink = s;   // keep loads alive; never taken

    } else if (b < B1_A0) {
        // ---- big gather
        const int gb    = b - B1_G0;
        const int n     = gb / 24;
        const int chunk = gb % 24;
        const float4* src = (const float4*)(pe0 + ((size_t)n * KB + label[n]) * (size_t)TB * HB);
        float4* dst = (float4*)(out + OFF_ENC + (size_t)n * TB * HB);
        const int i0 = chunk * 1024 + tid;
#pragma unroll
        for (int j = 0; j < 4; j++)
            dst[i0 + j * 256] = src[i0 + j * 256];

    } else if (b < B1_SM0) {
        // ---- A-GEMM: warp -> (4 h, 1 n); block shares the same 4 W rows
        const int wid  = tid >> 5;
        const int lane = tid & 31;
        const int gw   = (b - B1_A0) * 8 + wid;
        const int hg   = gw >> 5;
        const int n    = gw & 31;
        const int h0   = hg * 4;

        float4 a[12];
        const float4* arow0 = (const float4*)(ctx1 + (size_t)n * 3 * HB + 2 * HB);
        const float4* arow1 = (const float4*)(tku  + (size_t)n * HB);
#pragma unroll
        for (int i = 0; i < 6; i++) a[i]     = arow0[i * 32 + lane];
#pragma unroll
        for (int i = 0; i < 6; i++) a[i + 6] = arow1[i * 32 + lane];

        float acc[4];
#pragma unroll
        for (int hh = 0; hh < 4; hh++) {
            const float4* w = (const float4*)(Wcqk + (size_t)(h0 + hh) * H2);
            float s = 0.f;
#pragma unroll
            for (int i = 0; i < 12; i++) {
                float4 wv = w[i * 32 + lane];
                s += a[i].x * wv.x + a[i].y * wv.y + a[i].z * wv.z + a[i].w * wv.w;
            }
            acc[hh] = s;
        }
#pragma unroll
        for (int hh = 0; hh < 4; hh++) {
#pragma unroll
            for (int o = 16; o; o >>= 1)
                acc[hh] += __shfl_xor_sync(0xFFFFFFFFu, acc[hh], o);
        }
        if (lane == 0) {
            float* dst = cqkp + (size_t)n * HB + h0;
            dst[0] = acc[0] + bcqk[h0 + 0];
            dst[1] = acc[1] + bcqk[h0 + 1];
            dst[2] = acc[2] + bcqk[h0 + 2];
            dst[3] = acc[3] + bcqk[h0 + 3];
        }
    } else {
        // ---- small gathers
        const int n    = b - B1_SM0;
        const int lab  = label[n];
        const int base = (n * KB + lab) * TB;
        for (int t = tid; t < TB; t += 256) {
            out[OFF_MASK + n * TB + t] = (pm[base + t] != 0) ? 1.f : 0.f;
            out[OFF_IDX  + n * TB + t] = (float)pt[base + t];
        }
        const size_t ub = ((size_t)n * KB + lab) * HB;
        for (int h = tid; h < HB; h += 256)
            out[OFF_USE + n * HB + h] = pe1[ub + h];
    }
}

// ---------------------------------------------------------------------------
// Launch 2 (320 blocks x 256): dependency chain (Wk now L2-hot).
//   [0,192):   u partials (split-K, float4-dense warps; no spin).
//   [192,320): score — compute c[n]=bk.cqkp[n] AND prefetch pe1 BEFORE the
//              spin (both depend only on launch-1 data), spin on 192 u
//              producers, then sum partials and dot.
// ---------------------------------------------------------------------------
#define B2_U    192
#define B2_S0   192
#define GRID2   320
#define N_PROD  192

__global__ void __launch_bounds__(256) k2_chain(
    const float* __restrict__ cqkp,
    const float* __restrict__ Wk,
    const float* __restrict__ bk,
    const float* __restrict__ pe1,
    const int*   __restrict__ ckm,
    float* __restrict__ out)
{
    const int b    = blockIdx.x;
    const int tid  = threadIdx.x;
    const int wid  = tid >> 5;
    const int lane = tid & 31;

    if (b < B2_U) {
        // ---- u partial: b = htile*32 + split*4 + ngroup  (htile 0..5)
        const int htile = b >> 5;
        const int rem   = b & 31;
        const int split = rem >> 2;
        const int ng    = rem & 3;
        const int n     = ng * 8 + wid;
        const int h0    = htile * 128 + lane * 4;
        const int g0    = split * GCH;

        const float4* wrow = (const float4*)(Wk + (size_t)g0 * HB + h0);
        const float*  cr   = cqkp + (size_t)n * HB + g0;

        float4 acc0 = {0.f, 0.f, 0.f, 0.f};
        float4 acc1 = {0.f, 0.f, 0.f, 0.f};
#pragma unroll
        for (int gb = 0; gb < GCH; gb += 32) {
            float cg = cr[gb + lane];
            const float4* wb = wrow + (size_t)gb * (HB / 4);
#pragma unroll
            for (int j = 0; j < 32; j += 2) {
                float c0 = __shfl_sync(0xFFFFFFFFu, cg, j);
                float c1 = __shfl_sync(0xFFFFFFFFu, cg, j + 1);
                float4 w0 = wb[(size_t)j * (HB / 4)];
                float4 w1 = wb[(size_t)(j + 1) * (HB / 4)];
                acc0.x += c0 * w0.x; acc0.y += c0 * w0.y;
                acc0.z += c0 * w0.z; acc0.w += c0 * w0.w;
                acc1.x += c1 * w1.x; acc1.y += c1 * w1.y;
                acc1.z += c1 * w1.z; acc1.w += c1 * w1.w;
            }
        }
        float4 r;
        r.x = acc0.x + acc1.x; r.y = acc0.y + acc1.y;
        r.z = acc0.z + acc1.z; r.w = acc0.w + acc1.w;
        *(float4*)(&g_upart[split][n][h0]) = r;

        __threadfence();
        __syncthreads();
        if (tid == 0) atomicAdd(&g_cntU, 1u);

    } else {
        // ---- score block: (n, 8 k's); everything launch-1-dependent first
        const int bb = b - B2_S0;
        const int n  = bb >> 2;
        const int kg = bb & 3;
        const int k  = kg * 8 + wid;

        // prefetch pe1 row
        const float4* p = (const float4*)(pe1 + ((size_t)n * KB + k) * HB);
        float4 a[6];
#pragma unroll
        for (int i = 0; i < 6; i++) a[i] = p[i * 32 + lane];

        // c[n] = bk . cqkp[n]  (cqkp ready at launch start; L2-hot)
        const float4* cc  = (const float4*)(cqkp + (size_t)n * HB);
        const float4* bb4 = (const float4*)bk;
        float cpart = 0.f;
#pragma unroll
        for (int i = 0; i < 6; i++) {
            float4 x = cc[i * 32 + lane];
            float4 y = bb4[i * 32 + lane];
            cpart += x.x * y.x + x.y * y.y + x.z * y.z + x.w * y.w;
        }
#pragma unroll
        for (int o = 16; o; o >>= 1) cpart += __shfl_xor_sync(0xFFFFFFFFu, cpart, o);

        const int mask_v = ckm[n * KB + k];

        if (tid == 0) {
            while (ld_acq(&g_cntU) < (unsigned)N_PROD) __nanosleep(32);
        }
        __syncthreads();

        float s = 0.f;
#pragma unroll
        for (int i = 0; i < 6; i++) {
            const int hh = (i * 32 + lane) * 4;
            float4 q0 = *(const float4*)(&g_upart[0][n][hh]);
#pragma unroll
            for (int sp = 1; sp < USPLIT; sp++) {
                float4 qs = *(const float4*)(&g_upart[sp][n][hh]);
                q0.x += qs.x; q0.y += qs.y; q0.z += qs.z; q0.w += qs.w;
            }
            s += a[i].x * q0.x + a[i].y * q0.y + a[i].z * q0.z + a[i].w * q0.w;
        }
#pragma unroll
        for (int o = 16; o; o >>= 1) s += __shfl_xor_sync(0xFFFFFFFFu, s, o);
        if (lane == 0)
            out[OFF_SCORE + n * KB + k] = (mask_v != 0) ? (s + cpart) : -1e20f;
    }

    // ---- replay-safe reset: last block out clears the counters
    __syncthreads();
    if (tid == 0) {
        unsigned v = atomicAdd(&g_done, 1u);
        if (v == (unsigned)(GRID2 - 1)) {
            g_cntU = 0u;
            g_done = 0u;
            __threadfence();
        }
    }
}

extern "C" void kernel_launch(void* const* d_in, const int* in_sizes, int n_in,
                              void* d_out, int out_size)
{
    const float* ctx1 = (const float*)d_in[0];
    const float* tku  = (const float*)d_in[1];
    const float* pe0  = (const float*)d_in[2];
    const float* pe1  = (const float*)d_in[3];
    const int*   pm   = (const int*)d_in[4];
    const int*   ckm  = (const int*)d_in[5];
    const int*   lab  = (const int*)d_in[6];
    const int*   pt   = (const int*)d_in[7];
    const float* Wcqk = (const float*)d_in[8];
    const float* bcqk = (const float*)d_in[9];
    const float* Wk   = (const float*)d_in[10];
    const float* bk   = (const float*)d_in[11];

    float* out = (float*)d_out;

    float* d_cqkp; cudaGetSymbolAddress((void**)&d_cqkp, g_cqk_pro);

    k1_gather_agemm<<<GRID1, 256>>>(ctx1, tku, Wcqk, bcqk, pe0, pe1,
                                    pm, pt, lab, Wk, d_cqkp, out);
    k2_chain<<<GRID2, 256>>>(d_cqkp, Wk, bk, pe1, ckm, out);
}